// round 4
// baseline (speedup 1.0000x reference)
#include <cuda_runtime.h>
#include <cuda_fp16.h>
#include <cstdint>

// ---------------------------------------------------------------------------
// GroupLinear: out[t] = x[t] @ w[g].T ; token t in group g iff offs[g-1]<=t<offs[g]
// T=8192, G=8, K=1024, N=2048, fp32 in/out.
// fp32->fp16 convert pass, then mma.sync.m16n8k16 (HMMA) GEMM.
// R4: BM=128, BN=256, warp tile 64x64 (2m x 4n warps) -> LDSM bytes/FLOP halved.
// 3-stage cp.async pipeline, SW128 swizzle, 1 CTA/SM (144 KB smem).
// ---------------------------------------------------------------------------

#define T_TOK 8192
#define G_GRP 8
#define K_DIM 1024
#define N_DIM 2048

#define BM 128
#define BN 256
#define BK 64                    // fp16 elems per chunk = 128 B/row (SW128)
#define NCHUNK (K_DIM / BK)      // 16
#define STAGES 3

#define A_BYTES (BM * BK * 2)    // 16 KB
#define B_BYTES (BN * BK * 2)    // 32 KB
#define STAGE_BYTES (A_BYTES + B_BYTES)        // 48 KB
#define SMEM_TOTAL (STAGES * STAGE_BYTES)      // 144 KB

#define MAX_MTILES 71            // ceil(T/BM) + (G-1)
#define N_TILES (N_DIM / BN)     // 8

// fp16 scratch (device globals: allocation-free scratch per harness rules)
__device__ __align__(16) __half g_x16[(size_t)T_TOK * K_DIM];
__device__ __align__(16) __half g_w16[(size_t)G_GRP * N_DIM * K_DIM];

// ---------------------------------------------------------------------------
// helpers
// ---------------------------------------------------------------------------
static __device__ __forceinline__ uint32_t smem_u32(const void* p) {
    uint32_t a;
    asm("{ .reg .u64 t; cvta.to.shared.u64 t, %1; cvt.u32.u64 %0, t; }"
        : "=r"(a) : "l"(p));
    return a;
}

// SW128 swizzle on 128B rows, 16B chunks: chunk' = chunk ^ (row & 7)
static __device__ __forceinline__ uint32_t swz(uint32_t base, int row, int chunk) {
    return base + ((uint32_t)row << 7) + ((uint32_t)(chunk ^ (row & 7)) << 4);
}

static __device__ __forceinline__ void cp16(uint32_t dst, const void* src, uint32_t sz) {
    asm volatile("cp.async.cg.shared.global [%0], [%1], 16, %2;"
                 :: "r"(dst), "l"(src), "r"(sz));
}
static __device__ __forceinline__ void cp16f(uint32_t dst, const void* src) {
    asm volatile("cp.async.cg.shared.global [%0], [%1], 16;"
                 :: "r"(dst), "l"(src));
}

#define LDSM_X4(r, addr)                                                     \
    asm volatile("ldmatrix.sync.aligned.m8n8.x4.shared.b16 {%0,%1,%2,%3}, [%4];" \
        : "=r"((r)[0]), "=r"((r)[1]), "=r"((r)[2]), "=r"((r)[3]) : "r"(addr))

#define MMA16816(d, a, b0, b1)                                               \
    asm volatile("mma.sync.aligned.m16n8k16.row.col.f32.f16.f16.f32 "        \
        "{%0,%1,%2,%3}, {%4,%5,%6,%7}, {%8,%9}, {%0,%1,%2,%3};"              \
        : "+f"((d)[0]), "+f"((d)[1]), "+f"((d)[2]), "+f"((d)[3])             \
        : "r"((a)[0]), "r"((a)[1]), "r"((a)[2]), "r"((a)[3]),                \
          "r"(b0), "r"(b1))

// ---------------------------------------------------------------------------
// fp32 -> fp16 conversion kernels (more blocks -> more MLP, latency-bound fix)
// ---------------------------------------------------------------------------
__global__ void cvt_x_kernel(const float* __restrict__ src) {
    const int n4 = (T_TOK * K_DIM) / 4;
    int i = blockIdx.x * blockDim.x + threadIdx.x;
    int st = gridDim.x * blockDim.x;
    const float4* s4 = reinterpret_cast<const float4*>(src);
    uint2* d2 = reinterpret_cast<uint2*>(g_x16);
    for (; i < n4; i += st) {
        float4 v = s4[i];
        __half2 h0 = __floats2half2_rn(v.x, v.y);
        __half2 h1 = __floats2half2_rn(v.z, v.w);
        uint2 o;
        o.x = *reinterpret_cast<uint32_t*>(&h0);
        o.y = *reinterpret_cast<uint32_t*>(&h1);
        d2[i] = o;
    }
}

__global__ void cvt_w_kernel(const float* __restrict__ src) {
    const int n4 = (G_GRP * N_DIM * K_DIM) / 4;
    int i = blockIdx.x * blockDim.x + threadIdx.x;
    int st = gridDim.x * blockDim.x;
    const float4* s4 = reinterpret_cast<const float4*>(src);
    uint2* d2 = reinterpret_cast<uint2*>(g_w16);
    for (; i < n4; i += st) {
        float4 v = s4[i];
        __half2 h0 = __floats2half2_rn(v.x, v.y);
        __half2 h1 = __floats2half2_rn(v.z, v.w);
        uint2 o;
        o.x = *reinterpret_cast<uint32_t*>(&h0);
        o.y = *reinterpret_cast<uint32_t*>(&h1);
        d2[i] = o;
    }
}

// ---------------------------------------------------------------------------
// Grouped GEMM: 256 threads = 8 warps (2m x 4n), warp tile 64x64
// ---------------------------------------------------------------------------
extern "C" __global__ void __launch_bounds__(256, 1)
grouped_gemm_hmma(const int* __restrict__ offs, float* __restrict__ out) {
    // ---- map blockIdx.x -> (group, m_start, m_end) from device-side offs ----
    int gidx = blockIdx.x;
    const int n0 = blockIdx.y * BN;
    int g = -1, m_start = 0, m_end = 0, prev = 0;
#pragma unroll
    for (int gi = 0; gi < G_GRP; gi++) {
        int e = offs[gi];
        int mg = e - prev;
        int nt = (mg + BM - 1) >> 7;
        if (g < 0) {
            if (gidx < nt) { g = gi; m_start = prev + (gidx << 7); m_end = e; }
            else gidx -= nt;
        }
        prev = e;
    }
    if (g < 0) return;  // uniform per-CTA

    extern __shared__ __align__(1024) char smem[];
    const uint32_t sb = smem_u32(smem);

    const int tid = threadIdx.x;
    const int lane = tid & 31;
    const int wid = tid >> 5;
    const int wm = wid & 1;        // 0..1  (m warp: 64 rows each)
    const int wn = wid >> 1;       // 0..3  (n warp: 64 cols each)

    const __half* xA = g_x16 + (size_t)m_start * K_DIM;
    const __half* wB = g_w16 + ((size_t)g * N_DIM + n0) * K_DIM;

    // ---- producer: load chunk j into stage s (all 256 threads) ----
    auto load_stage = [&](int j, int s) {
        const uint32_t a_base = sb + s * STAGE_BYTES;
        const uint32_t b_base = a_base + A_BYTES;
        const int k0 = j * BK;
#pragma unroll
        for (int p = 0; p < 4; p++) {          // A: 128 rows x 8 chunks = 1024
            int lin = tid + p * 256;
            int r = lin >> 3;
            int c = lin & 7;
            cp16(swz(a_base, r, c), xA + (size_t)r * K_DIM + k0 + c * 8,
                 (m_start + r < T_TOK) ? 16u : 0u);
        }
#pragma unroll
        for (int p = 0; p < 8; p++) {          // B: 256 rows x 8 chunks = 2048
            int lin = tid + p * 256;
            int r = lin >> 3;
            int c = lin & 7;
            cp16f(swz(b_base, r, c), wB + (size_t)r * K_DIM + k0 + c * 8);
        }
        asm volatile("cp.async.commit_group;" ::: "memory");
    };

    load_stage(0, 0);
    load_stage(1, 1);

    float acc[4][8][4] = {};

    for (int j = 0; j < NCHUNK; j++) {
        const int s = j % STAGES;
        asm volatile("cp.async.wait_group %0;" :: "n"(STAGES - 2) : "memory");
        __syncthreads();

        if (j + STAGES - 1 < NCHUNK) load_stage(j + STAGES - 1, (j + STAGES - 1) % STAGES);
        else asm volatile("cp.async.commit_group;" ::: "memory");

        const uint32_t a_base = sb + s * STAGE_BYTES;
        const uint32_t b_base = a_base + A_BYTES;

#pragma unroll
        for (int ks = 0; ks < 4; ks++) {            // 4 x k16 per chunk
            uint32_t af[4][4];
#pragma unroll
            for (int mi = 0; mi < 4; mi++) {        // 4 x m16
                int row = wm * 64 + mi * 16 + (lane & 15);
                int ch = ks * 2 + (lane >> 4);
                LDSM_X4(af[mi], swz(a_base, row, ch));
            }
            uint32_t bf[4][4];
#pragma unroll
            for (int np = 0; np < 4; np++) {        // 4 x n16
                // non-trans B: lanes 0-7 -> (n 0-7, k 0-7), 8-15 -> (n 0-7, k 8-15),
                //              16-23 -> (n 8-15, k 0-7), 24-31 -> (n 8-15, k 8-15)
                int row = wn * 64 + np * 16 + ((lane >> 4) << 3) + (lane & 7);
                int ch = ks * 2 + ((lane >> 3) & 1);
                LDSM_X4(bf[np], swz(b_base, row, ch));
            }
#pragma unroll
            for (int mi = 0; mi < 4; mi++)
#pragma unroll
                for (int np = 0; np < 4; np++) {
                    MMA16816(acc[mi][np * 2 + 0], af[mi], bf[np][0], bf[np][1]);
                    MMA16816(acc[mi][np * 2 + 1], af[mi], bf[np][2], bf[np][3]);
                }
        }
    }

    // ---- epilogue: masked fp32 stores ----
#pragma unroll
    for (int mi = 0; mi < 4; mi++) {
        const int r0 = m_start + wm * 64 + mi * 16 + (lane >> 2);
        const int r1 = r0 + 8;
#pragma unroll
        for (int ni = 0; ni < 8; ni++) {
            const int col = n0 + wn * 64 + ni * 8 + (lane & 3) * 2;
            if (r0 < m_end)
                *reinterpret_cast<float2*>(out + (size_t)r0 * N_DIM + col) =
                    make_float2(acc[mi][ni][0], acc[mi][ni][1]);
            if (r1 < m_end)
                *reinterpret_cast<float2*>(out + (size_t)r1 * N_DIM + col) =
                    make_float2(acc[mi][ni][2], acc[mi][ni][3]);
        }
    }
}

// ---------------------------------------------------------------------------
// kernel_launch
// ---------------------------------------------------------------------------
extern "C" void kernel_launch(void* const* d_in, const int* in_sizes, int n_in,
                              void* d_out, int out_size) {
    const float* x  = (const float*)d_in[0];   // [8192, 1024]
    const float* w  = (const float*)d_in[1];   // [8, 2048, 1024]
    const int* offs = (const int*)d_in[2];     // [8]
    float* out      = (float*)d_out;           // [8192, 2048]

    cudaFuncSetAttribute(grouped_gemm_hmma,
                         cudaFuncAttributeMaxDynamicSharedMemorySize, SMEM_TOTAL);

    cvt_x_kernel<<<4096, 256>>>(x);            // ~2 float4 per thread
    cvt_w_kernel<<<8192, 256>>>(w);            // ~2 float4 per thread
    grouped_gemm_hmma<<<dim3(MAX_MTILES, N_TILES), 256, SMEM_TOTAL>>>(offs, out);
}

// round 5
// speedup vs baseline: 1.0999x; 1.0999x over previous
#include <cuda_runtime.h>
#include <cuda_fp16.h>
#include <cstdint>

// ---------------------------------------------------------------------------
// GroupLinear: out[t] = x[t] @ w[g].T ; token t in group g iff offs[g-1]<=t<offs[g]
// T=8192, G=8, K=1024, N=2048, fp32 in/out.
// fp32->fp16 convert (single merged kernel), then mma.sync.m16n8k16 GEMM.
// R5: GEMM = R3 config (BM=BN=128, 4m x 2n warps, 3-stage cp.async, 2 CTA/SM).
//     Conversions merged into one kernel (2x chip MLP); streaming epilogue.
// ---------------------------------------------------------------------------

#define T_TOK 8192
#define G_GRP 8
#define K_DIM 1024
#define N_DIM 2048

#define BM 128
#define BN 128
#define BK 64                    // fp16 elems per chunk = 128 B/row (SW128)
#define NCHUNK (K_DIM / BK)      // 16
#define STAGES 3

#define A_BYTES (BM * BK * 2)    // 16 KB
#define B_BYTES (BN * BK * 2)    // 16 KB
#define STAGE_BYTES (A_BYTES + B_BYTES)        // 32 KB
#define SMEM_TOTAL (STAGES * STAGE_BYTES)      // 96 KB

#define MAX_MTILES 71            // ceil(T/BM) + (G-1)
#define N_TILES (N_DIM / BN)     // 16

// fp16 scratch (device globals: allocation-free scratch per harness rules)
__device__ __align__(16) __half g_x16[(size_t)T_TOK * K_DIM];
__device__ __align__(16) __half g_w16[(size_t)G_GRP * N_DIM * K_DIM];

// ---------------------------------------------------------------------------
// helpers
// ---------------------------------------------------------------------------
static __device__ __forceinline__ uint32_t smem_u32(const void* p) {
    uint32_t a;
    asm("{ .reg .u64 t; cvta.to.shared.u64 t, %1; cvt.u32.u64 %0, t; }"
        : "=r"(a) : "l"(p));
    return a;
}

// SW128 swizzle on 128B rows, 16B chunks: chunk' = chunk ^ (row & 7)
static __device__ __forceinline__ uint32_t swz(uint32_t base, int row, int chunk) {
    return base + ((uint32_t)row << 7) + ((uint32_t)(chunk ^ (row & 7)) << 4);
}

static __device__ __forceinline__ void cp16(uint32_t dst, const void* src, uint32_t sz) {
    asm volatile("cp.async.cg.shared.global [%0], [%1], 16, %2;"
                 :: "r"(dst), "l"(src), "r"(sz));
}
static __device__ __forceinline__ void cp16f(uint32_t dst, const void* src) {
    asm volatile("cp.async.cg.shared.global [%0], [%1], 16;"
                 :: "r"(dst), "l"(src));
}

#define LDSM_X4(r, addr)                                                     \
    asm volatile("ldmatrix.sync.aligned.m8n8.x4.shared.b16 {%0,%1,%2,%3}, [%4];" \
        : "=r"((r)[0]), "=r"((r)[1]), "=r"((r)[2]), "=r"((r)[3]) : "r"(addr))

#define MMA16816(d, a, b0, b1)                                               \
    asm volatile("mma.sync.aligned.m16n8k16.row.col.f32.f16.f16.f32 "        \
        "{%0,%1,%2,%3}, {%4,%5,%6,%7}, {%8,%9}, {%0,%1,%2,%3};"              \
        : "+f"((d)[0]), "+f"((d)[1]), "+f"((d)[2]), "+f"((d)[3])             \
        : "r"((a)[0]), "r"((a)[1]), "r"((a)[2]), "r"((a)[3]),                \
          "r"(b0), "r"(b1))

// streaming store (evict-first): out is write-only, keep L2 for x16/w16
static __device__ __forceinline__ void st_cs_f2(float* p, float a, float b) {
    float2 v = make_float2(a, b);
    asm volatile("st.global.cs.v2.f32 [%0], {%1, %2};"
                 :: "l"(p), "f"(v.x), "f"(v.y) : "memory");
}

// ---------------------------------------------------------------------------
// merged fp32 -> fp16 conversion kernel: x (8M floats) then w (16M floats)
// each thread: 2 x float4 loads -> 1 x uint4 (16B) store per iteration
// ---------------------------------------------------------------------------
#define X_FLOATS (T_TOK * K_DIM)                     // 8 M
#define W_FLOATS (G_GRP * N_DIM * K_DIM)             // 16 M
#define CVT_N8 ((X_FLOATS + W_FLOATS) / 8)           // 3 M iterations of 8 floats

__global__ void cvt_all_kernel(const float* __restrict__ x,
                               const float* __restrict__ w) {
    int i = blockIdx.x * blockDim.x + threadIdx.x;
    const int st = gridDim.x * blockDim.x;
    const int xn8 = X_FLOATS / 8;
    for (; i < CVT_N8; i += st) {
        const float4* s4;
        uint4* d4;
        if (i < xn8) {
            s4 = reinterpret_cast<const float4*>(x) + i * 2;
            d4 = reinterpret_cast<uint4*>(g_x16) + i;
        } else {
            int j = i - xn8;
            s4 = reinterpret_cast<const float4*>(w) + j * 2;
            d4 = reinterpret_cast<uint4*>(g_w16) + j;
        }
        float4 v0 = s4[0];
        float4 v1 = s4[1];
        __half2 h0 = __floats2half2_rn(v0.x, v0.y);
        __half2 h1 = __floats2half2_rn(v0.z, v0.w);
        __half2 h2 = __floats2half2_rn(v1.x, v1.y);
        __half2 h3 = __floats2half2_rn(v1.z, v1.w);
        uint4 o;
        o.x = *reinterpret_cast<uint32_t*>(&h0);
        o.y = *reinterpret_cast<uint32_t*>(&h1);
        o.z = *reinterpret_cast<uint32_t*>(&h2);
        o.w = *reinterpret_cast<uint32_t*>(&h3);
        *d4 = o;
    }
}

// ---------------------------------------------------------------------------
// Grouped GEMM, mma.sync fp16, 256 threads = 8 warps (4m x 2n), warp = 32x64
// ---------------------------------------------------------------------------
extern "C" __global__ void __launch_bounds__(256, 2)
grouped_gemm_hmma(const int* __restrict__ offs, float* __restrict__ out) {
    // ---- map blockIdx.x -> (group, m_start, m_end) from device-side offs ----
    int gidx = blockIdx.x;
    const int n0 = blockIdx.y * BN;
    int g = -1, m_start = 0, m_end = 0, prev = 0;
#pragma unroll
    for (int gi = 0; gi < G_GRP; gi++) {
        int e = offs[gi];
        int mg = e - prev;
        int nt = (mg + BM - 1) >> 7;
        if (g < 0) {
            if (gidx < nt) { g = gi; m_start = prev + (gidx << 7); m_end = e; }
            else gidx -= nt;
        }
        prev = e;
    }
    if (g < 0) return;  // uniform per-CTA

    extern __shared__ __align__(1024) char smem[];
    const uint32_t sb = smem_u32(smem);

    const int tid = threadIdx.x;
    const int lane = tid & 31;
    const int wid = tid >> 5;
    const int wm = wid & 3;        // 0..3  (m warp)
    const int wn = wid >> 2;       // 0..1  (n warp)

    const __half* xA = g_x16 + (size_t)m_start * K_DIM;
    const __half* wB = g_w16 + ((size_t)g * N_DIM + n0) * K_DIM;

    // ---- producer: load chunk j into stage s (all 256 threads, 8 x 16B each) ----
    auto load_stage = [&](int j, int s) {
        const uint32_t a_base = sb + s * STAGE_BYTES;
        const uint32_t b_base = a_base + A_BYTES;
        const int k0 = j * BK;
#pragma unroll
        for (int p = 0; p < 4; p++) {
            int lin = tid + p * 256;        // 0..1023
            int r = lin >> 3;               // 0..127
            int c = lin & 7;                // 16B chunk
            cp16(swz(a_base, r, c), xA + (size_t)r * K_DIM + k0 + c * 8,
                 (m_start + r < T_TOK) ? 16u : 0u);
            cp16f(swz(b_base, r, c), wB + (size_t)r * K_DIM + k0 + c * 8);
        }
        asm volatile("cp.async.commit_group;" ::: "memory");
    };

    load_stage(0, 0);
    load_stage(1, 1);

    float acc[2][8][4] = {};

    for (int j = 0; j < NCHUNK; j++) {
        const int s = j % STAGES;
        asm volatile("cp.async.wait_group %0;" :: "n"(STAGES - 2) : "memory");
        __syncthreads();   // stage s data visible; all warps done with stage (j+2)%3

        if (j + STAGES - 1 < NCHUNK) load_stage(j + STAGES - 1, (j + STAGES - 1) % STAGES);
        else asm volatile("cp.async.commit_group;" ::: "memory");

        const uint32_t a_base = sb + s * STAGE_BYTES;
        const uint32_t b_base = a_base + A_BYTES;

#pragma unroll
        for (int ks = 0; ks < 4; ks++) {            // 4 x k16 per chunk
            uint32_t af[2][4];
#pragma unroll
            for (int mi = 0; mi < 2; mi++) {
                int row = wm * 32 + mi * 16 + (lane & 15);
                int ch = ks * 2 + (lane >> 4);
                LDSM_X4(af[mi], swz(a_base, row, ch));
            }
            uint32_t bf[4][4];
#pragma unroll
            for (int np = 0; np < 4; np++) {        // 4 x n16
                // non-trans B: lanes 0-7 -> (n 0-7, k 0-7), 8-15 -> (n 0-7, k 8-15),
                //              16-23 -> (n 8-15, k 0-7), 24-31 -> (n 8-15, k 8-15)
                int row = wn * 64 + np * 16 + ((lane >> 4) << 3) + (lane & 7);
                int ch = ks * 2 + ((lane >> 3) & 1);
                LDSM_X4(bf[np], swz(b_base, row, ch));
            }
#pragma unroll
            for (int mi = 0; mi < 2; mi++)
#pragma unroll
                for (int np = 0; np < 4; np++) {
                    MMA16816(acc[mi][np * 2 + 0], af[mi], bf[np][0], bf[np][1]);
                    MMA16816(acc[mi][np * 2 + 1], af[mi], bf[np][2], bf[np][3]);
                }
        }
    }

    // ---- epilogue: masked fp32 streaming stores ----
#pragma unroll
    for (int mi = 0; mi < 2; mi++) {
        const int r0 = m_start + wm * 32 + mi * 16 + (lane >> 2);
        const int r1 = r0 + 8;
#pragma unroll
        for (int ni = 0; ni < 8; ni++) {
            const int col = n0 + wn * 64 + ni * 8 + (lane & 3) * 2;
            if (r0 < m_end)
                st_cs_f2(out + (size_t)r0 * N_DIM + col,
                         acc[mi][ni][0], acc[mi][ni][1]);
            if (r1 < m_end)
                st_cs_f2(out + (size_t)r1 * N_DIM + col,
                         acc[mi][ni][2], acc[mi][ni][3]);
        }
    }
}

// ---------------------------------------------------------------------------
// kernel_launch
// ---------------------------------------------------------------------------
extern "C" void kernel_launch(void* const* d_in, const int* in_sizes, int n_in,
                              void* d_out, int out_size) {
    const float* x  = (const float*)d_in[0];   // [8192, 1024]
    const float* w  = (const float*)d_in[1];   // [8, 2048, 1024]
    const int* offs = (const int*)d_in[2];     // [8]
    float* out      = (float*)d_out;           // [8192, 2048]

    cudaFuncSetAttribute(grouped_gemm_hmma,
                         cudaFuncAttributeMaxDynamicSharedMemorySize, SMEM_TOTAL);

    cvt_all_kernel<<<4096, 256>>>(x, w);       // ~3 iters of 8 floats per thread
    grouped_gemm_hmma<<<dim3(MAX_MTILES, N_TILES), 256, SMEM_TOTAL>>>(offs, out);
}